// round 7
// baseline (speedup 1.0000x reference)
#include <cuda_runtime.h>
#include <cuda_bf16.h>
#include <cstdint>

// ---------------- problem constants ----------------
#define NQ   50000
#define NMS  50000
#define NH   32
#define NK   15
#define NC   64
#define ND   64
#define KPAD 50048          // NQ padded to multiple of 128
#define KC2  1024           // 64 channels * 16 (k padded 15->16)

// scratch: hi/lo bf16 planes of weighted[n][c*16+k] (normalization folded in)
__device__ __nv_bfloat16 g_hi[(size_t)KPAD * KC2];   // ~102 MB
__device__ __nv_bfloat16 g_lo[(size_t)KPAD * KC2];   // ~102 MB
__device__ uint4         g_bfrag[64 * 8 * 32];       // B fragments, 256 KB
__device__ float         g_flag[NMS];                // rowsum>0 flags

// ---------------- helpers ----------------
__device__ __forceinline__ unsigned long long ffma2(unsigned long long a,
                                                    unsigned long long b,
                                                    unsigned long long c) {
    unsigned long long d;
    asm("fma.rn.f32x2 %0, %1, %2, %3;" : "=l"(d) : "l"(a), "l"(b), "l"(c));
    return d;
}
__device__ __forceinline__ unsigned long long add2(unsigned long long a,
                                                   unsigned long long b) {
    unsigned long long d;
    asm("add.rn.f32x2 %0, %1, %2;" : "=l"(d) : "l"(a), "l"(b));
    return d;
}
__device__ __forceinline__ unsigned long long splat2(float v) {
    unsigned long long d;
    asm("mov.b64 %0, {%1, %1};" : "=l"(d) : "f"(v));
    return d;
}
__device__ __forceinline__ float2 unpack2(unsigned long long v) {
    float2 r;
    asm("mov.b64 {%0, %1}, %2;" : "=f"(r.x), "=f"(r.y) : "l"(v));
    return r;
}
__device__ __forceinline__ unsigned long long mul2(unsigned long long a,
                                                   unsigned long long b) {
    unsigned long long d;
    asm("mul.rn.f32x2 %0, %1, %2;" : "=l"(d) : "l"(a), "l"(b));
    return d;
}
// pack bf16x2: low half = x (first elem in memory), high = y
__device__ __forceinline__ uint32_t pack_bf16x2(float x, float y) {
    uint32_t r;
    asm("cvt.rn.bf16x2.f32 %0, %1, %2;" : "=r"(r) : "f"(y), "f"(x));
    return r;
}
__device__ __forceinline__ uint32_t smem_u32(const void* p) {
    uint32_t a;
    asm("{ .reg .u64 t; cvta.to.shared.u64 t, %1; cvt.u32.u64 %0, t; }" : "=r"(a) : "l"(p));
    return a;
}
__device__ __forceinline__ void cp16(uint32_t dst, const void* src) {
    asm volatile("cp.async.cg.shared.global [%0], [%1], 16;" :: "r"(dst), "l"(src));
}
#define CP_COMMIT() asm volatile("cp.async.commit_group;" ::: "memory")
#define CP_WAIT0()  asm volatile("cp.async.wait_group 0;" ::: "memory")
#define CP_WAIT1()  asm volatile("cp.async.wait_group 1;" ::: "memory")
#define SWZ(o) ((o) ^ (((o) >> 3) & 0x70))

__device__ __forceinline__ void ldsm4(uint32_t& r0, uint32_t& r1, uint32_t& r2,
                                      uint32_t& r3, uint32_t addr) {
    asm volatile("ldmatrix.sync.aligned.m8n8.x4.shared.b16 {%0,%1,%2,%3}, [%4];"
        : "=r"(r0), "=r"(r1), "=r"(r2), "=r"(r3) : "r"(addr));
}
__device__ __forceinline__ void mma16816(float* d, const uint32_t* a,
                                         uint32_t b0, uint32_t b1) {
    asm volatile(
        "mma.sync.aligned.m16n8k16.row.col.f32.bf16.bf16.f32 "
        "{%0,%1,%2,%3}, {%4,%5,%6,%7}, {%8,%9}, {%0,%1,%2,%3};"
        : "+f"(d[0]), "+f"(d[1]), "+f"(d[2]), "+f"(d[3])
        : "r"(a[0]), "r"(a[1]), "r"(a[2]), "r"(a[3]), "r"(b0), "r"(b1));
}

// =============================================================================
// prep A: validity flags f[m] = (sum_c x[m,c] > 0)
// =============================================================================
__global__ void __launch_bounds__(256) prep_flags(const float* __restrict__ x) {
    const int w = threadIdx.x >> 5, l = threadIdx.x & 31;
    const int r = blockIdx.x * 16 + w * 2 + (l >> 4);
    const float4 v = ((const float4*)(x + (size_t)r * NC))[l & 15];
    float s = v.x + v.y + v.z + v.w;
    #pragma unroll
    for (int o = 1; o < 16; o <<= 1) s += __shfl_xor_sync(0xffffffffu, s, o);
    if ((l & 15) == 0) g_flag[r] = (s > 0.0f) ? 1.0f : 0.0f;
}

// =============================================================================
// prep B: pack W into m16n8k16 B-fragment order.
//   B[kc][n] = W[k_kp][c][n],  kc = c*16 + k_kp  (k_kp==15 -> 0 pad)
// =============================================================================
__device__ __forceinline__ float wval(const float* W, int kc, int n) {
    const int k_kp = kc & 15, c = kc >> 4;
    return (k_kp < NK) ? W[((size_t)k_kp * NC + c) * ND + n] : 0.0f;
}
__global__ void __launch_bounds__(256) prep_w(const float* __restrict__ W) {
    const int g     = blockIdx.x * 256 + threadIdx.x;   // 64*8*32 = 16384
    const int lane  = g & 31;
    const int ntile = (g >> 5) & 7;
    const int kstep = g >> 8;                           // 0..63
    const int n  = ntile * 8 + (lane >> 2);
    const int kc = kstep * 16 + 2 * (lane & 3);
    float v[4] = { wval(W, kc,     n), wval(W, kc + 1, n),
                   wval(W, kc + 8, n), wval(W, kc + 9, n) };
    float h[4], l[4];
    #pragma unroll
    for (int i = 0; i < 4; i++) {
        h[i] = __bfloat162float(__float2bfloat16(v[i]));
        l[i] = v[i] - h[i];
    }
    g_bfrag[g] = make_uint4(pack_bf16x2(h[0], h[1]), pack_bf16x2(h[2], h[3]),
                            pack_bf16x2(l[0], l[1]), pack_bf16x2(l[2], l[3]));
}

// =============================================================================
// Stage 1 (v3): 2 warps per query, each owning 16 of the 32 neighbors.
// Block = 256 threads = 8 warps = 4 queries.
// Phase A: lanes 0..15 of each warp compute w[h][k] for its 16 h.
// Phase B: lane = channel (c=lane, c+32), 16 f32x2 k-pair accumulators,
//          16 h iterations (half the R5 latency chain).
// Reduce:  odd warp dumps accs to smem [j][lane] (conflict-free);
//          even warp adds and runs the R5 epilogue.
// =============================================================================
__global__ void __launch_bounds__(256, 2) kpconv_stage1(
    const float* __restrict__ q_pts, const float* __restrict__ s_pts,
    const int*   __restrict__ nbi,   const float* __restrict__ x,
    const float* __restrict__ kp)
{
    __shared__ __align__(16) float ws[8][16][16];        // 16 KB
    __shared__ int idxs[8][16];
    __shared__ int cnts[8];
    __shared__ __align__(16) unsigned long long red[4][16][32];   // 16 KB

    const int warp = threadIdx.x >> 5;   // 0..7
    const int lane = threadIdx.x & 31;
    const int qloc = warp >> 1;          // 0..3
    const int hw   = warp & 1;           // which h-half this warp owns
    const int n    = blockIdx.x * 4 + qloc;

    // ---- phase A: lanes 0..15, h_local = lane ----
    float vf = 0.0f;
    if (lane < 16) {
        const int h   = hw * 16 + lane;
        const int idx = __ldg(&nbi[n * NH + h]);
        const float qx = q_pts[n*3+0], qy = q_pts[n*3+1], qz = q_pts[n*3+2];
        const float dx = __ldg(&s_pts[idx*3+0]) - qx;
        const float dy = __ldg(&s_pts[idx*3+1]) - qy;
        const float dz = __ldg(&s_pts[idx*3+2]) - qz;
        vf = __ldg(&g_flag[idx]);
        #pragma unroll
        for (int k = 0; k < NK; k++) {
            const float ex = dx - kp[k*3+0];
            const float ey = dy - kp[k*3+1];
            const float ez = dz - kp[k*3+2];
            const float d2 = ex*ex + ey*ey + ez*ez;
            const float r  = __frsqrt_rn(fmaxf(d2, 1e-24f));
            ws[warp][lane][k] = fmaxf(1.0f - (d2 * r) * (1.0f / 1.2f), 0.0f);
        }
        ws[warp][lane][15] = 0.0f;
        idxs[warp][lane] = idx;
    }
    const int cnt_half = __popc(__ballot_sync(0xffffffffu, vf > 0.0f));
    if (lane == 0) cnts[warp] = cnt_half;
    __syncthreads();

    // ---- phase B: 16 h iterations, lane = channels (lane, lane+32) ----
    unsigned long long a0[8], a1[8];
    #pragma unroll
    for (int j = 0; j < 8; j++) { a0[j] = 0ull; a1[j] = 0ull; }

    #pragma unroll
    for (int h = 0; h < 16; h++) {
        const int ih = idxs[warp][h];
        const float* xr = x + (size_t)ih * NC;
        const unsigned long long xx0 = splat2(__ldg(&xr[lane]));
        const unsigned long long xx1 = splat2(__ldg(&xr[lane + 32]));
        const ulonglong2* wp = (const ulonglong2*)&ws[warp][h][0];
        #pragma unroll
        for (int j = 0; j < 4; j++) {
            const ulonglong2 w2 = wp[j];
            a0[2*j+0] = ffma2(w2.x, xx0, a0[2*j+0]);
            a0[2*j+1] = ffma2(w2.y, xx0, a0[2*j+1]);
            a1[2*j+0] = ffma2(w2.x, xx1, a1[2*j+0]);
            a1[2*j+1] = ffma2(w2.y, xx1, a1[2*j+1]);
        }
    }

    // ---- pair reduction ----
    if (hw == 1) {
        #pragma unroll
        for (int j = 0; j < 8; j++) {
            red[qloc][j][lane]     = a0[j];
            red[qloc][j + 8][lane] = a1[j];
        }
    }
    __syncthreads();
    if (hw == 1) return;

    #pragma unroll
    for (int j = 0; j < 8; j++) {
        a0[j] = add2(a0[j], red[qloc][j][lane]);
        a1[j] = add2(a1[j], red[qloc][j + 8][lane]);
    }

    const int cnt = cnts[qloc*2] + cnts[qloc*2 + 1];
    const float inv = 1.0f / (float)(cnt > 0 ? cnt : 1);
    const unsigned long long inv2 = splat2(inv);

    // ---- epilogue (R5): normalize, hi/lo split, STG.128 x8 ----
    #pragma unroll
    for (int half = 0; half < 2; half++) {
        const int c = lane + half * 32;
        const unsigned long long* acc = half ? a1 : a0;
        uint32_t hi[8], lo[8];
        #pragma unroll
        for (int j = 0; j < 8; j++) {
            const float2 s = unpack2(mul2(acc[j], inv2));
            const uint32_t hp = pack_bf16x2(s.x, s.y);
            const __nv_bfloat162 hb = *(const __nv_bfloat162*)&hp;
            const float2 hf = __bfloat1622float2(hb);
            hi[j] = hp;
            lo[j] = pack_bf16x2(s.x - hf.x, s.y - hf.y);
        }
        const size_t base = (size_t)n * KC2 + c * 16;
        uint4* ph = (uint4*)(g_hi + base);
        uint4* pl = (uint4*)(g_lo + base);
        ph[0] = make_uint4(hi[0], hi[1], hi[2], hi[3]);
        ph[1] = make_uint4(hi[4], hi[5], hi[6], hi[7]);
        pl[0] = make_uint4(lo[0], lo[1], lo[2], lo[3]);
        pl[1] = make_uint4(lo[4], lo[5], lo[6], lo[7]);
    }
}

// =============================================================================
// Stage 2: out[KPAD,64] via mma.sync split-bf16 (AhBh + AhBl + AlBh).
// (unchanged from R5/R6 — 65 us, tensor=57%)
// =============================================================================
#define S2_THREADS 256
#define BUFB 49152
#define OFF_ALO 16384
#define OFF_BF  32768
#define SM_TOT  (2 * BUFB)

__device__ __forceinline__ void s2_issue(uint32_t sb, int buf, int chunk, int tid,
                                         const char* Ahi, const char* Alo) {
    const uint32_t base = sb + buf * BUFB;
    #pragma unroll
    for (int i = 0; i < 8; i++) {                 // A: 2 planes x 128 rows x 128B
        const int ch   = i * S2_THREADS + tid;    // 0..2047
        const int rr   = (ch >> 3) & 127;
        const int c16  = (ch & 7) * 16;
        const uint32_t d = SWZ((uint32_t)(rr * 128 + c16));
        const size_t  src = (size_t)rr * 2048 + chunk * 128 + c16;
        if (i < 4) cp16(base + d, Ahi + src);
        else       cp16(base + OFF_ALO + d, Alo + src);
    }
    #pragma unroll
    for (int i = 0; i < 4; i++) {                 // B frags: 16 KB linear
        const int ch = i * S2_THREADS + tid;      // 0..1023
        cp16(base + OFF_BF + ch * 16, (const char*)g_bfrag + ((size_t)chunk * 1024 + ch) * 16);
    }
}

__global__ void __launch_bounds__(S2_THREADS) kpconv_stage2(float* __restrict__ out) {
    extern __shared__ __align__(1024) char smem[];
    const uint32_t sb = smem_u32(smem);
    const int tid  = threadIdx.x;
    const int wid  = tid >> 5;
    const int lane = tid & 31;
    const int n0   = blockIdx.x * 128;
    const int m0   = wid * 16;

    const char* Ahi = (const char*)(g_hi + (size_t)n0 * KC2);
    const char* Alo = (const char*)(g_lo + (size_t)n0 * KC2);

    float d[8][4];
    #pragma unroll
    for (int t = 0; t < 8; t++)
        #pragma unroll
        for (int j = 0; j < 4; j++) d[t][j] = 0.0f;

    const uint32_t arow = (uint32_t)(m0 + (lane & 15));
    const uint32_t ahalf = (uint32_t)((lane >> 4) * 16);   // bytes

    s2_issue(sb, 0, 0, tid, Ahi, Alo);
    CP_COMMIT();

    for (int ch = 0; ch < 16; ch++) {
        if (ch + 1 < 16) {
            s2_issue(sb, (ch + 1) & 1, ch + 1, tid, Ahi, Alo);
            CP_COMMIT();
            CP_WAIT1();
        } else {
            CP_WAIT0();
        }
        __syncthreads();

        const uint32_t base = sb + (ch & 1) * BUFB;
        #pragma unroll
        for (int ks = 0; ks < 4; ks++) {
            const uint32_t aoff = SWZ(arow * 128 + (uint32_t)(ks * 32) + ahalf);
            uint32_t ah[4], al[4];
            ldsm4(ah[0], ah[1], ah[2], ah[3], base + aoff);
            ldsm4(al[0], al[1], al[2], al[3], base + OFF_ALO + aoff);
            const uint32_t bbase = base + OFF_BF + (uint32_t)(ks * 8 * 32 + lane) * 16;
            #pragma unroll
            for (int nt = 0; nt < 8; nt++) {
                uint4 bf;
                asm volatile("ld.shared.v4.b32 {%0,%1,%2,%3}, [%4];"
                    : "=r"(bf.x), "=r"(bf.y), "=r"(bf.z), "=r"(bf.w)
                    : "r"(bbase + (uint32_t)(nt * 32 * 16)));
                mma16816(d[nt], ah, bf.x, bf.y);   // Ahi * Bhi
                mma16816(d[nt], ah, bf.z, bf.w);   // Ahi * Blo
                mma16816(d[nt], al, bf.x, bf.y);   // Alo * Bhi
            }
        }
        __syncthreads();
    }

    const int r0 = n0 + m0 + (lane >> 2);
    const int r1 = r0 + 8;
    const int c0 = (lane & 3) * 2;
    #pragma unroll
    for (int nt = 0; nt < 8; nt++) {
        const int c = nt * 8 + c0;
        if (r0 < NQ) *(float2*)(out + (size_t)r0 * ND + c) = make_float2(d[nt][0], d[nt][1]);
        if (r1 < NQ) *(float2*)(out + (size_t)r1 * ND + c) = make_float2(d[nt][2], d[nt][3]);
    }
}

// =============================================================================
extern "C" void kernel_launch(void* const* d_in, const int* in_sizes, int n_in,
                              void* d_out, int out_size) {
    const float* q_pts = (const float*)d_in[0];
    const float* s_pts = (const float*)d_in[1];
    const int*   nbi   = (const int*)  d_in[2];
    const float* x     = (const float*)d_in[3];
    const float* kp    = (const float*)d_in[4];
    const float* W     = (const float*)d_in[5];
    float* out = (float*)d_out;

    cudaFuncSetAttribute(kpconv_stage2, cudaFuncAttributeMaxDynamicSharedMemorySize, SM_TOT);

    prep_flags<<<NMS / 16, 256>>>(x);
    prep_w<<<64, 256>>>(W);
    kpconv_stage1<<<NQ / 4, 256>>>(q_pts, s_pts, nbi, x, kp);
    kpconv_stage2<<<KPAD / 128, S2_THREADS, SM_TOT>>>(out);
}

// round 8
// speedup vs baseline: 1.1324x; 1.1324x over previous
#include <cuda_runtime.h>
#include <cuda_bf16.h>
#include <cstdint>

// ---------------- problem constants ----------------
#define NQ   50000
#define NMS  50000
#define NH   32
#define NK   15
#define NC   64
#define ND   64
#define KPAD 50048          // NQ padded to multiple of 128
#define KC2  1024           // 64 channels * 16 (k padded 15->16)

// scratch: hi/lo bf16 planes of weighted[n][c*16+k] (normalization folded in)
__device__ __nv_bfloat16 g_hi[(size_t)KPAD * KC2];   // ~102 MB
__device__ __nv_bfloat16 g_lo[(size_t)KPAD * KC2];   // ~102 MB
__device__ uint4         g_bfrag[64 * 8 * 32];       // B fragments, 256 KB
__device__ float         g_flag[NMS];                // rowsum>0 flags

// ---------------- helpers ----------------
__device__ __forceinline__ unsigned long long ffma2(unsigned long long a,
                                                    unsigned long long b,
                                                    unsigned long long c) {
    unsigned long long d;
    asm("fma.rn.f32x2 %0, %1, %2, %3;" : "=l"(d) : "l"(a), "l"(b), "l"(c));
    return d;
}
__device__ __forceinline__ unsigned long long splat2(float v) {
    unsigned long long d;
    asm("mov.b64 %0, {%1, %1};" : "=l"(d) : "f"(v));
    return d;
}
__device__ __forceinline__ float2 unpack2(unsigned long long v) {
    float2 r;
    asm("mov.b64 {%0, %1}, %2;" : "=f"(r.x), "=f"(r.y) : "l"(v));
    return r;
}
__device__ __forceinline__ unsigned long long mul2(unsigned long long a,
                                                   unsigned long long b) {
    unsigned long long d;
    asm("mul.rn.f32x2 %0, %1, %2;" : "=l"(d) : "l"(a), "l"(b));
    return d;
}
// pack bf16x2: low half = x (first elem in memory), high = y
__device__ __forceinline__ uint32_t pack_bf16x2(float x, float y) {
    uint32_t r;
    asm("cvt.rn.bf16x2.f32 %0, %1, %2;" : "=r"(r) : "f"(y), "f"(x));
    return r;
}
__device__ __forceinline__ uint32_t smem_u32(const void* p) {
    uint32_t a;
    asm("{ .reg .u64 t; cvta.to.shared.u64 t, %1; cvt.u32.u64 %0, t; }" : "=r"(a) : "l"(p));
    return a;
}
__device__ __forceinline__ void cp16(uint32_t dst, const void* src) {
    asm volatile("cp.async.cg.shared.global [%0], [%1], 16;" :: "r"(dst), "l"(src));
}
#define CP_COMMIT() asm volatile("cp.async.commit_group;" ::: "memory")
#define CP_WAIT0()  asm volatile("cp.async.wait_group 0;" ::: "memory")
#define CP_WAIT1()  asm volatile("cp.async.wait_group 1;" ::: "memory")
#define SWZ(o) ((o) ^ (((o) >> 3) & 0x70))

__device__ __forceinline__ void ldsm4(uint32_t& r0, uint32_t& r1, uint32_t& r2,
                                      uint32_t& r3, uint32_t addr) {
    asm volatile("ldmatrix.sync.aligned.m8n8.x4.shared.b16 {%0,%1,%2,%3}, [%4];"
        : "=r"(r0), "=r"(r1), "=r"(r2), "=r"(r3) : "r"(addr));
}
__device__ __forceinline__ void mma16816(float* d, const uint32_t* a,
                                         uint32_t b0, uint32_t b1) {
    asm volatile(
        "mma.sync.aligned.m16n8k16.row.col.f32.bf16.bf16.f32 "
        "{%0,%1,%2,%3}, {%4,%5,%6,%7}, {%8,%9}, {%0,%1,%2,%3};"
        : "+f"(d[0]), "+f"(d[1]), "+f"(d[2]), "+f"(d[3])
        : "r"(a[0]), "r"(a[1]), "r"(a[2]), "r"(a[3]), "r"(b0), "r"(b1));
}

// =============================================================================
// prep A: validity flags f[m] = (sum_c x[m,c] > 0)
// =============================================================================
__global__ void __launch_bounds__(256) prep_flags(const float* __restrict__ x) {
    const int w = threadIdx.x >> 5, l = threadIdx.x & 31;
    const int r = blockIdx.x * 16 + w * 2 + (l >> 4);
    const float4 v = ((const float4*)(x + (size_t)r * NC))[l & 15];
    float s = v.x + v.y + v.z + v.w;
    #pragma unroll
    for (int o = 1; o < 16; o <<= 1) s += __shfl_xor_sync(0xffffffffu, s, o);
    if ((l & 15) == 0) g_flag[r] = (s > 0.0f) ? 1.0f : 0.0f;
}

// =============================================================================
// prep B: pack W into m16n8k16 B-fragment order.
//   B[kc][n] = W[k_kp][c][n],  kc = c*16 + k_kp  (k_kp==15 -> 0 pad)
// =============================================================================
__device__ __forceinline__ float wval(const float* W, int kc, int n) {
    const int k_kp = kc & 15, c = kc >> 4;
    return (k_kp < NK) ? W[((size_t)k_kp * NC + c) * ND + n] : 0.0f;
}
__global__ void __launch_bounds__(256) prep_w(const float* __restrict__ W) {
    const int g     = blockIdx.x * 256 + threadIdx.x;   // 64*8*32 = 16384
    const int lane  = g & 31;
    const int ntile = (g >> 5) & 7;
    const int kstep = g >> 8;                           // 0..63
    const int n  = ntile * 8 + (lane >> 2);
    const int kc = kstep * 16 + 2 * (lane & 3);
    float v[4] = { wval(W, kc,     n), wval(W, kc + 1, n),
                   wval(W, kc + 8, n), wval(W, kc + 9, n) };
    float h[4], l[4];
    #pragma unroll
    for (int i = 0; i < 4; i++) {
        h[i] = __bfloat162float(__float2bfloat16(v[i]));
        l[i] = v[i] - h[i];
    }
    g_bfrag[g] = make_uint4(pack_bf16x2(h[0], h[1]), pack_bf16x2(h[2], h[3]),
                            pack_bf16x2(l[0], l[1]), pack_bf16x2(l[2], l[3]));
}

// =============================================================================
// Stage 1 (v4): R5 shape (1 warp/query, 16 f32x2 accs) + cp.async-staged
// x-gathers. Phase B runs 4 groups of 8 neighbors, double-buffered in the
// warp's private smem x-buffer (2 x 2KB). Lane owns channels 2*lane, 2*lane+1
// -> one LDS.64 per h, fully contiguous 64B epilogue stores per plane.
// Dynamic smem: ws 16K | idxs 1K | pad | xbuf 32K = 50176 B.
// =============================================================================
#define S1_WS    0
#define S1_IDX   16384
#define S1_XBUF  17408
#define S1_SMEM  (S1_XBUF + 8 * 2 * 2048)   // 50176

__device__ __forceinline__ void s1_stage(uint32_t sb, const int* idxw,
                                         const float* x, int g, int buf,
                                         int warp, int lane) {
    const uint32_t dstb = sb + S1_XBUF + (uint32_t)((warp * 2 + buf) * 2048);
    #pragma unroll
    for (int i = 0; i < 4; i++) {
        const int idx16 = i * 32 + lane;        // 0..127 16B-chunks
        const int row   = idx16 >> 4;           // 0..7 neighbor in group
        const int off   = (idx16 & 15) * 16;    // byte offset in 256B row
        const int ih    = idxw[g * 8 + row];
        cp16(dstb + (uint32_t)(idx16 * 16),
             (const char*)x + (size_t)ih * 256 + off);
    }
}

__global__ void __launch_bounds__(256) kpconv_stage1(
    const float* __restrict__ q_pts, const float* __restrict__ s_pts,
    const int*   __restrict__ nbi,   const float* __restrict__ x,
    const float* __restrict__ kp)
{
    extern __shared__ __align__(16) char s1mem[];
    float* ws   = (float*)(s1mem + S1_WS);      // [8][32][16]
    int*   idxs = (int*)  (s1mem + S1_IDX);     // [8][32]
    const uint32_t sb = smem_u32(s1mem);

    const int warp = threadIdx.x >> 5;
    const int lane = threadIdx.x & 31;
    const int n    = blockIdx.x * 8 + warp;
    float* wsw = ws + warp * 32 * 16;
    int*  idxw = idxs + warp * 32;

    // ---- phase A: lane = neighbor h ----
    const int idx = __ldg(&nbi[n * NH + lane]);
    const float qx = q_pts[n*3+0], qy = q_pts[n*3+1], qz = q_pts[n*3+2];
    const float dx = __ldg(&s_pts[idx*3+0]) - qx;
    const float dy = __ldg(&s_pts[idx*3+1]) - qy;
    const float dz = __ldg(&s_pts[idx*3+2]) - qz;
    const float vf = __ldg(&g_flag[idx]);
    #pragma unroll
    for (int k = 0; k < NK; k++) {
        const float ex = dx - kp[k*3+0];
        const float ey = dy - kp[k*3+1];
        const float ez = dz - kp[k*3+2];
        const float d2 = ex*ex + ey*ey + ez*ez;
        const float r  = __frsqrt_rn(fmaxf(d2, 1e-24f));
        wsw[lane * 16 + k] = fmaxf(1.0f - (d2 * r) * (1.0f / 1.2f), 0.0f);
    }
    wsw[lane * 16 + 15] = 0.0f;
    idxw[lane] = idx;
    const int cnt = __popc(__ballot_sync(0xffffffffu, vf > 0.0f));
    __syncwarp();

    // ---- phase B: 4 groups of 8 h, double-buffered cp.async staging ----
    unsigned long long a0[8], a1[8];   // k-pairs for channels 2*lane, 2*lane+1
    #pragma unroll
    for (int j = 0; j < 8; j++) { a0[j] = 0ull; a1[j] = 0ull; }

    s1_stage(sb, idxw, x, 0, 0, warp, lane);
    CP_COMMIT();

    const char* xbw = s1mem + S1_XBUF + warp * 2 * 2048;
    #pragma unroll
    for (int g = 0; g < 4; g++) {
        if (g < 3) {
            s1_stage(sb, idxw, x, g + 1, (g + 1) & 1, warp, lane);
            CP_COMMIT();
            CP_WAIT1();
        } else {
            CP_WAIT0();
        }
        __syncwarp();   // all lanes' cp.async for this buffer complete

        const char* buf = xbw + (g & 1) * 2048;
        #pragma unroll
        for (int hh = 0; hh < 8; hh++) {
            const float2 xx = *(const float2*)(buf + hh * 256 + lane * 8);
            const unsigned long long xx0 = splat2(xx.x);
            const unsigned long long xx1 = splat2(xx.y);
            const ulonglong2* wp = (const ulonglong2*)(wsw + (g * 8 + hh) * 16);
            #pragma unroll
            for (int j = 0; j < 4; j++) {
                const ulonglong2 w2 = wp[j];
                a0[2*j+0] = ffma2(w2.x, xx0, a0[2*j+0]);
                a0[2*j+1] = ffma2(w2.y, xx0, a0[2*j+1]);
                a1[2*j+0] = ffma2(w2.x, xx1, a1[2*j+0]);
                a1[2*j+1] = ffma2(w2.y, xx1, a1[2*j+1]);
            }
        }
        __syncwarp();   // compute done before next issue overwrites buffer
    }

    const float inv = 1.0f / (float)(cnt > 0 ? cnt : 1);
    const unsigned long long inv2 = splat2(inv);

    // ---- epilogue: channels c0=2*lane, c0+1 -> 64B contiguous per plane ----
    uint32_t hi[16], lo[16];
    #pragma unroll
    for (int half = 0; half < 2; half++) {
        const unsigned long long* acc = half ? a1 : a0;
        #pragma unroll
        for (int j = 0; j < 8; j++) {
            const float2 s = unpack2(mul2(acc[j], inv2));
            const uint32_t hp = pack_bf16x2(s.x, s.y);
            const __nv_bfloat162 hb = *(const __nv_bfloat162*)&hp;
            const float2 hf = __bfloat1622float2(hb);
            hi[half * 8 + j] = hp;
            lo[half * 8 + j] = pack_bf16x2(s.x - hf.x, s.y - hf.y);
        }
    }
    const size_t base = (size_t)n * KC2 + (size_t)(2 * lane) * 16;
    uint4* ph = (uint4*)(g_hi + base);
    uint4* pl = (uint4*)(g_lo + base);
    #pragma unroll
    for (int q = 0; q < 4; q++) {
        ph[q] = make_uint4(hi[4*q], hi[4*q+1], hi[4*q+2], hi[4*q+3]);
        pl[q] = make_uint4(lo[4*q], lo[4*q+1], lo[4*q+2], lo[4*q+3]);
    }
}

// =============================================================================
// Stage 2: out[KPAD,64] via mma.sync split-bf16 (AhBh + AhBl + AlBh).
// (unchanged from R5 — 65 us, tensor=57%)
// =============================================================================
#define S2_THREADS 256
#define BUFB 49152
#define OFF_ALO 16384
#define OFF_BF  32768
#define SM_TOT  (2 * BUFB)

__device__ __forceinline__ void s2_issue(uint32_t sb, int buf, int chunk, int tid,
                                         const char* Ahi, const char* Alo) {
    const uint32_t base = sb + buf * BUFB;
    #pragma unroll
    for (int i = 0; i < 8; i++) {                 // A: 2 planes x 128 rows x 128B
        const int ch   = i * S2_THREADS + tid;    // 0..2047
        const int rr   = (ch >> 3) & 127;
        const int c16  = (ch & 7) * 16;
        const uint32_t d = SWZ((uint32_t)(rr * 128 + c16));
        const size_t  src = (size_t)rr * 2048 + chunk * 128 + c16;
        if (i < 4) cp16(base + d, Ahi + src);
        else       cp16(base + OFF_ALO + d, Alo + src);
    }
    #pragma unroll
    for (int i = 0; i < 4; i++) {                 // B frags: 16 KB linear
        const int ch = i * S2_THREADS + tid;      // 0..1023
        cp16(base + OFF_BF + ch * 16, (const char*)g_bfrag + ((size_t)chunk * 1024 + ch) * 16);
    }
}

__global__ void __launch_bounds__(S2_THREADS) kpconv_stage2(float* __restrict__ out) {
    extern __shared__ __align__(1024) char smem[];
    const uint32_t sb = smem_u32(smem);
    const int tid  = threadIdx.x;
    const int wid  = tid >> 5;
    const int lane = tid & 31;
    const int n0   = blockIdx.x * 128;
    const int m0   = wid * 16;

    const char* Ahi = (const char*)(g_hi + (size_t)n0 * KC2);
    const char* Alo = (const char*)(g_lo + (size_t)n0 * KC2);

    float d[8][4];
    #pragma unroll
    for (int t = 0; t < 8; t++)
        #pragma unroll
        for (int j = 0; j < 4; j++) d[t][j] = 0.0f;

    const uint32_t arow = (uint32_t)(m0 + (lane & 15));
    const uint32_t ahalf = (uint32_t)((lane >> 4) * 16);   // bytes

    s2_issue(sb, 0, 0, tid, Ahi, Alo);
    CP_COMMIT();

    for (int ch = 0; ch < 16; ch++) {
        if (ch + 1 < 16) {
            s2_issue(sb, (ch + 1) & 1, ch + 1, tid, Ahi, Alo);
            CP_COMMIT();
            CP_WAIT1();
        } else {
            CP_WAIT0();
        }
        __syncthreads();

        const uint32_t base = sb + (ch & 1) * BUFB;
        #pragma unroll
        for (int ks = 0; ks < 4; ks++) {
            const uint32_t aoff = SWZ(arow * 128 + (uint32_t)(ks * 32) + ahalf);
            uint32_t ah[4], al[4];
            ldsm4(ah[0], ah[1], ah[2], ah[3], base + aoff);
            ldsm4(al[0], al[1], al[2], al[3], base + OFF_ALO + aoff);
            const uint32_t bbase = base + OFF_BF + (uint32_t)(ks * 8 * 32 + lane) * 16;
            #pragma unroll
            for (int nt = 0; nt < 8; nt++) {
                uint4 bf;
                asm volatile("ld.shared.v4.b32 {%0,%1,%2,%3}, [%4];"
                    : "=r"(bf.x), "=r"(bf.y), "=r"(bf.z), "=r"(bf.w)
                    : "r"(bbase + (uint32_t)(nt * 32 * 16)));
                mma16816(d[nt], ah, bf.x, bf.y);   // Ahi * Bhi
                mma16816(d[nt], ah, bf.z, bf.w);   // Ahi * Blo
                mma16816(d[nt], al, bf.x, bf.y);   // Alo * Bhi
            }
        }
        __syncthreads();
    }

    const int r0 = n0 + m0 + (lane >> 2);
    const int r1 = r0 + 8;
    const int c0 = (lane & 3) * 2;
    #pragma unroll
    for (int nt = 0; nt < 8; nt++) {
        const int c = nt * 8 + c0;
        if (r0 < NQ) *(float2*)(out + (size_t)r0 * ND + c) = make_float2(d[nt][0], d[nt][1]);
        if (r1 < NQ) *(float2*)(out + (size_t)r1 * ND + c) = make_float2(d[nt][2], d[nt][3]);
    }
}

// =============================================================================
extern "C" void kernel_launch(void* const* d_in, const int* in_sizes, int n_in,
                              void* d_out, int out_size) {
    const float* q_pts = (const float*)d_in[0];
    const float* s_pts = (const float*)d_in[1];
    const int*   nbi   = (const int*)  d_in[2];
    const float* x     = (const float*)d_in[3];
    const float* kp    = (const float*)d_in[4];
    const float* W     = (const float*)d_in[5];
    float* out = (float*)d_out;

    cudaFuncSetAttribute(kpconv_stage1, cudaFuncAttributeMaxDynamicSharedMemorySize, S1_SMEM);
    cudaFuncSetAttribute(kpconv_stage2, cudaFuncAttributeMaxDynamicSharedMemorySize, SM_TOT);

    prep_flags<<<NMS / 16, 256>>>(x);
    prep_w<<<64, 256>>>(W);
    kpconv_stage1<<<NQ / 8, 256, S1_SMEM>>>(q_pts, s_pts, nbi, x, kp);
    kpconv_stage2<<<KPAD / 128, S2_THREADS, SM_TOT>>>(out);
}

// round 9
// speedup vs baseline: 1.1682x; 1.0316x over previous
#include <cuda_runtime.h>
#include <cuda_bf16.h>
#include <cstdint>

// ---------------- problem constants ----------------
#define NQ   50000
#define NMS  50000
#define NH   32
#define NK   15
#define NC   64
#define ND   64
#define KPAD 50048          // NQ padded to multiple of 128
#define KC2  1024           // 64 channels * 16 (k padded 15->16)

// scratch: hi/lo bf16 planes of weighted[n][c*16+k] (normalization folded in)
__device__ __nv_bfloat16 g_hi[(size_t)KPAD * KC2];   // ~102 MB
__device__ __nv_bfloat16 g_lo[(size_t)KPAD * KC2];   // ~102 MB
__device__ uint4         g_bfrag[64 * 8 * 32];       // B fragments, 256 KB
__device__ float         g_flag[NMS];                // rowsum>0 flags

// ---------------- helpers ----------------
__device__ __forceinline__ unsigned long long ffma2(unsigned long long a,
                                                    unsigned long long b,
                                                    unsigned long long c) {
    unsigned long long d;
    asm("fma.rn.f32x2 %0, %1, %2, %3;" : "=l"(d) : "l"(a), "l"(b), "l"(c));
    return d;
}
__device__ __forceinline__ unsigned long long splat2(float v) {
    unsigned long long d;
    asm("mov.b64 %0, {%1, %1};" : "=l"(d) : "f"(v));
    return d;
}
__device__ __forceinline__ float2 unpack2(unsigned long long v) {
    float2 r;
    asm("mov.b64 {%0, %1}, %2;" : "=f"(r.x), "=f"(r.y) : "l"(v));
    return r;
}
__device__ __forceinline__ unsigned long long mul2(unsigned long long a,
                                                   unsigned long long b) {
    unsigned long long d;
    asm("mul.rn.f32x2 %0, %1, %2;" : "=l"(d) : "l"(a), "l"(b));
    return d;
}
// pack bf16x2: low half = x (first elem in memory), high = y
__device__ __forceinline__ uint32_t pack_bf16x2(float x, float y) {
    uint32_t r;
    asm("cvt.rn.bf16x2.f32 %0, %1, %2;" : "=r"(r) : "f"(y), "f"(x));
    return r;
}
__device__ __forceinline__ uint32_t smem_u32(const void* p) {
    uint32_t a;
    asm("{ .reg .u64 t; cvta.to.shared.u64 t, %1; cvt.u32.u64 %0, t; }" : "=r"(a) : "l"(p));
    return a;
}
__device__ __forceinline__ void cp16(uint32_t dst, const void* src) {
    asm volatile("cp.async.cg.shared.global [%0], [%1], 16;" :: "r"(dst), "l"(src));
}
#define CP_COMMIT() asm volatile("cp.async.commit_group;" ::: "memory")
#define CP_WAIT0()  asm volatile("cp.async.wait_group 0;" ::: "memory")
#define CP_WAIT1()  asm volatile("cp.async.wait_group 1;" ::: "memory")
#define SWZ(o) ((o) ^ (((o) >> 3) & 0x70))

__device__ __forceinline__ void ldsm4(uint32_t& r0, uint32_t& r1, uint32_t& r2,
                                      uint32_t& r3, uint32_t addr) {
    asm volatile("ldmatrix.sync.aligned.m8n8.x4.shared.b16 {%0,%1,%2,%3}, [%4];"
        : "=r"(r0), "=r"(r1), "=r"(r2), "=r"(r3) : "r"(addr));
}
__device__ __forceinline__ void mma16816(float* d, const uint32_t* a,
                                         uint32_t b0, uint32_t b1) {
    asm volatile(
        "mma.sync.aligned.m16n8k16.row.col.f32.bf16.bf16.f32 "
        "{%0,%1,%2,%3}, {%4,%5,%6,%7}, {%8,%9}, {%0,%1,%2,%3};"
        : "+f"(d[0]), "+f"(d[1]), "+f"(d[2]), "+f"(d[3])
        : "r"(a[0]), "r"(a[1]), "r"(a[2]), "r"(a[3]), "r"(b0), "r"(b1));
}

// =============================================================================
// prep A: validity flags f[m] = (sum_c x[m,c] > 0)
// =============================================================================
__global__ void __launch_bounds__(256) prep_flags(const float* __restrict__ x) {
    const int w = threadIdx.x >> 5, l = threadIdx.x & 31;
    const int r = blockIdx.x * 16 + w * 2 + (l >> 4);
    const float4 v = ((const float4*)(x + (size_t)r * NC))[l & 15];
    float s = v.x + v.y + v.z + v.w;
    #pragma unroll
    for (int o = 1; o < 16; o <<= 1) s += __shfl_xor_sync(0xffffffffu, s, o);
    if ((l & 15) == 0) g_flag[r] = (s > 0.0f) ? 1.0f : 0.0f;
}

// =============================================================================
// prep B: pack W into m16n8k16 B-fragment order.
//   B[kc][n] = W[k_kp][c][n],  kc = c*16 + k_kp  (k_kp==15 -> 0 pad)
// =============================================================================
__device__ __forceinline__ float wval(const float* W, int kc, int n) {
    const int k_kp = kc & 15, c = kc >> 4;
    return (k_kp < NK) ? W[((size_t)k_kp * NC + c) * ND + n] : 0.0f;
}
__global__ void __launch_bounds__(256) prep_w(const float* __restrict__ W) {
    const int g     = blockIdx.x * 256 + threadIdx.x;   // 64*8*32 = 16384
    const int lane  = g & 31;
    const int ntile = (g >> 5) & 7;
    const int kstep = g >> 8;                           // 0..63
    const int n  = ntile * 8 + (lane >> 2);
    const int kc = kstep * 16 + 2 * (lane & 3);
    float v[4] = { wval(W, kc,     n), wval(W, kc + 1, n),
                   wval(W, kc + 8, n), wval(W, kc + 9, n) };
    float h[4], l[4];
    #pragma unroll
    for (int i = 0; i < 4; i++) {
        h[i] = __bfloat162float(__float2bfloat16(v[i]));
        l[i] = v[i] - h[i];
    }
    g_bfrag[g] = make_uint4(pack_bf16x2(h[0], h[1]), pack_bf16x2(h[2], h[3]),
                            pack_bf16x2(l[0], l[1]), pack_bf16x2(l[2], l[3]));
}

// =============================================================================
// Stage 1 (R5 shape, consolidated): 1 warp/query, 8 queries/block.
// Phase A: lane = neighbor h -> w[h][k] in smem.
// Phase B: lane = channels (2*lane, 2*lane+1): ONE LDG.64 per x-row per h,
// 16 f32x2 k-pair accumulators, unroll 8.
// Epilogue: contiguous 4x STG.128 per plane per lane.
// =============================================================================
__global__ void __launch_bounds__(256) kpconv_stage1(
    const float* __restrict__ q_pts, const float* __restrict__ s_pts,
    const int*   __restrict__ nbi,   const float* __restrict__ x,
    const float* __restrict__ kp)
{
    __shared__ __align__(16) float ws[8][NH][16];   // 16 KB
    __shared__ int idxs[8][NH];
    const int warp = threadIdx.x >> 5;
    const int lane = threadIdx.x & 31;
    const int n    = blockIdx.x * 8 + warp;

    // ---- phase A: lane = neighbor h ----
    const int idx = __ldg(&nbi[n * NH + lane]);
    const float qx = q_pts[n*3+0], qy = q_pts[n*3+1], qz = q_pts[n*3+2];
    const float dx = __ldg(&s_pts[idx*3+0]) - qx;
    const float dy = __ldg(&s_pts[idx*3+1]) - qy;
    const float dz = __ldg(&s_pts[idx*3+2]) - qz;
    const float vf = __ldg(&g_flag[idx]);
    #pragma unroll
    for (int k = 0; k < NK; k++) {
        const float ex = dx - kp[k*3+0];
        const float ey = dy - kp[k*3+1];
        const float ez = dz - kp[k*3+2];
        const float d2 = ex*ex + ey*ey + ez*ez;
        const float r  = __frsqrt_rn(fmaxf(d2, 1e-24f));
        ws[warp][lane][k] = fmaxf(1.0f - (d2 * r) * (1.0f / 1.2f), 0.0f);
    }
    ws[warp][lane][15] = 0.0f;
    idxs[warp][lane] = idx;
    const int cnt = __popc(__ballot_sync(0xffffffffu, vf > 0.0f));
    __syncwarp();

    // ---- phase B: lane owns channels 2*lane, 2*lane+1 ----
    unsigned long long a0[8], a1[8];
    #pragma unroll
    for (int j = 0; j < 8; j++) { a0[j] = 0ull; a1[j] = 0ull; }

    #pragma unroll 8
    for (int h = 0; h < NH; h++) {
        const int ih = idxs[warp][h];
        const float2 xx = __ldg((const float2*)(x + (size_t)ih * NC) + lane);
        const unsigned long long xx0 = splat2(xx.x);
        const unsigned long long xx1 = splat2(xx.y);
        const ulonglong2* wp = (const ulonglong2*)&ws[warp][h][0];
        #pragma unroll
        for (int j = 0; j < 4; j++) {
            const ulonglong2 w2 = wp[j];
            a0[2*j+0] = ffma2(w2.x, xx0, a0[2*j+0]);
            a0[2*j+1] = ffma2(w2.y, xx0, a0[2*j+1]);
            a1[2*j+0] = ffma2(w2.x, xx1, a1[2*j+0]);
            a1[2*j+1] = ffma2(w2.y, xx1, a1[2*j+1]);
        }
    }

    const float inv = 1.0f / (float)(cnt > 0 ? cnt : 1);
    const unsigned long long inv2 = splat2(inv);

    // ---- epilogue: channels 2*lane, 2*lane+1 -> contiguous 128B per plane ----
    uint32_t hi[16], lo[16];
    #pragma unroll
    for (int half = 0; half < 2; half++) {
        const unsigned long long* acc = half ? a1 : a0;
        #pragma unroll
        for (int j = 0; j < 8; j++) {
            const float2 s = unpack2(mul2(acc[j], inv2));
            const uint32_t hp = pack_bf16x2(s.x, s.y);
            const __nv_bfloat162 hb = *(const __nv_bfloat162*)&hp;
            const float2 hf = __bfloat1622float2(hb);
            hi[half * 8 + j] = hp;
            lo[half * 8 + j] = pack_bf16x2(s.x - hf.x, s.y - hf.y);
        }
    }
    const size_t base = (size_t)n * KC2 + (size_t)(2 * lane) * 16;
    uint4* ph = (uint4*)(g_hi + base);
    uint4* pl = (uint4*)(g_lo + base);
    #pragma unroll
    for (int q = 0; q < 4; q++) {
        ph[q] = make_uint4(hi[4*q], hi[4*q+1], hi[4*q+2], hi[4*q+3]);
        pl[q] = make_uint4(lo[4*q], lo[4*q+1], lo[4*q+2], lo[4*q+3]);
    }
}

// =============================================================================
// Stage 2 (v2): BM=64 for 3 blocks/SM. Block = 64 rows x 64 cols.
// 8 warps: m-tile = (wid&3)*16, n-half = (wid>>2)*32 (4 n-tiles of 8).
// 16 double-buffered cp.async chunks of kc=64; 12 MMAs/warp/ks.
// Smem per buffer: A_hi 8K | A_lo 8K | Bfrag 16K = 32K; x2 = 64 KB.
// =============================================================================
#define S2_THREADS 256
#define BUFB 32768
#define OFF_ALO 8192
#define OFF_BF  16384
#define SM_TOT  (2 * BUFB)

__device__ __forceinline__ void s2_issue(uint32_t sb, int buf, int chunk, int tid,
                                         const char* Ahi, const char* Alo) {
    const uint32_t base = sb + buf * BUFB;
    #pragma unroll
    for (int i = 0; i < 4; i++) {                 // A: 2 planes x 64 rows x 128B
        const int ch  = i * S2_THREADS + tid;     // 0..1023
        const int rr  = (ch >> 3) & 63;
        const int c16 = (ch & 7) * 16;
        const uint32_t d = SWZ((uint32_t)(rr * 128 + c16));
        const size_t src = (size_t)rr * 2048 + chunk * 128 + c16;
        if (i < 2) cp16(base + d, Ahi + src);
        else       cp16(base + OFF_ALO + d, Alo + src);
    }
    #pragma unroll
    for (int i = 0; i < 4; i++) {                 // B frags: 16 KB linear
        const int ch = i * S2_THREADS + tid;      // 0..1023
        cp16(base + OFF_BF + ch * 16, (const char*)g_bfrag + ((size_t)chunk * 1024 + ch) * 16);
    }
}

__global__ void __launch_bounds__(S2_THREADS) kpconv_stage2(float* __restrict__ out) {
    extern __shared__ __align__(1024) char smem[];
    const uint32_t sb = smem_u32(smem);
    const int tid   = threadIdx.x;
    const int wid   = tid >> 5;
    const int lane  = tid & 31;
    const int n0    = blockIdx.x * 64;
    const int m0    = (wid & 3) * 16;
    const int nhalf = wid >> 2;          // 0 or 1: n-tiles nhalf*4 .. nhalf*4+3

    const char* Ahi = (const char*)(g_hi + (size_t)n0 * KC2);
    const char* Alo = (const char*)(g_lo + (size_t)n0 * KC2);

    float d[4][4];
    #pragma unroll
    for (int t = 0; t < 4; t++)
        #pragma unroll
        for (int j = 0; j < 4; j++) d[t][j] = 0.0f;

    const uint32_t arow  = (uint32_t)(m0 + (lane & 15));
    const uint32_t ahalf = (uint32_t)((lane >> 4) * 16);   // bytes

    s2_issue(sb, 0, 0, tid, Ahi, Alo);
    CP_COMMIT();

    for (int ch = 0; ch < 16; ch++) {
        if (ch + 1 < 16) {
            s2_issue(sb, (ch + 1) & 1, ch + 1, tid, Ahi, Alo);
            CP_COMMIT();
            CP_WAIT1();
        } else {
            CP_WAIT0();
        }
        __syncthreads();

        const uint32_t base = sb + (ch & 1) * BUFB;
        #pragma unroll
        for (int ks = 0; ks < 4; ks++) {
            const uint32_t aoff = SWZ(arow * 128 + (uint32_t)(ks * 32) + ahalf);
            uint32_t ah[4], al[4];
            ldsm4(ah[0], ah[1], ah[2], ah[3], base + aoff);
            ldsm4(al[0], al[1], al[2], al[3], base + OFF_ALO + aoff);
            const uint32_t bbase = base + OFF_BF +
                (uint32_t)((ks * 8 + nhalf * 4) * 32 + lane) * 16;
            #pragma unroll
            for (int nt = 0; nt < 4; nt++) {
                uint4 bf;
                asm volatile("ld.shared.v4.b32 {%0,%1,%2,%3}, [%4];"
                    : "=r"(bf.x), "=r"(bf.y), "=r"(bf.z), "=r"(bf.w)
                    : "r"(bbase + (uint32_t)(nt * 32 * 16)));
                mma16816(d[nt], ah, bf.x, bf.y);   // Ahi * Bhi
                mma16816(d[nt], ah, bf.z, bf.w);   // Ahi * Blo
                mma16816(d[nt], al, bf.x, bf.y);   // Alo * Bhi
            }
        }
        __syncthreads();
    }

    const int r0 = n0 + m0 + (lane >> 2);
    const int r1 = r0 + 8;
    const int c0 = (lane & 3) * 2;
    #pragma unroll
    for (int nt = 0; nt < 4; nt++) {
        const int c = (nhalf * 4 + nt) * 8 + c0;
        if (r0 < NQ) *(float2*)(out + (size_t)r0 * ND + c) = make_float2(d[nt][0], d[nt][1]);
        if (r1 < NQ) *(float2*)(out + (size_t)r1 * ND + c) = make_float2(d[nt][2], d[nt][3]);
    }
}

// =============================================================================
extern "C" void kernel_launch(void* const* d_in, const int* in_sizes, int n_in,
                              void* d_out, int out_size) {
    const float* q_pts = (const float*)d_in[0];
    const float* s_pts = (const float*)d_in[1];
    const int*   nbi   = (const int*)  d_in[2];
    const float* x     = (const float*)d_in[3];
    const float* kp    = (const float*)d_in[4];
    const float* W     = (const float*)d_in[5];
    float* out = (float*)d_out;

    cudaFuncSetAttribute(kpconv_stage2, cudaFuncAttributeMaxDynamicSharedMemorySize, SM_TOT);

    prep_flags<<<NMS / 16, 256>>>(x);
    prep_w<<<64, 256>>>(W);
    kpconv_stage1<<<NQ / 8, 256>>>(q_pts, s_pts, nbi, x, kp);
    kpconv_stage2<<<KPAD / 64, S2_THREADS, SM_TOT>>>(out);
}

// round 10
// speedup vs baseline: 1.4213x; 1.2166x over previous
#include <cuda_runtime.h>
#include <cuda_fp16.h>
#include <cuda_bf16.h>
#include <cstdint>

// ---------------- problem constants ----------------
#define NQ   50000
#define NMS  50000
#define NH   32
#define NK   15
#define NC   64
#define ND   64
#define KPAD 50048          // NQ padded to multiple of 128
#define KC2  1024           // 64 channels * 16 (k padded 15->16)

// scratch: SINGLE fp16 plane of weighted[n][c*16+k] (normalization folded in)
__device__ __half g_a[(size_t)KPAD * KC2];           // ~102 MB
__device__ uint4  g_bfrag[64 * 8 * 32];              // B fp16 hi/lo fragments, 256 KB
__device__ float  g_flag[NMS];                       // rowsum>0 flags

// ---------------- helpers ----------------
__device__ __forceinline__ unsigned long long ffma2(unsigned long long a,
                                                    unsigned long long b,
                                                    unsigned long long c) {
    unsigned long long d;
    asm("fma.rn.f32x2 %0, %1, %2, %3;" : "=l"(d) : "l"(a), "l"(b), "l"(c));
    return d;
}
__device__ __forceinline__ unsigned long long splat2(float v) {
    unsigned long long d;
    asm("mov.b64 %0, {%1, %1};" : "=l"(d) : "f"(v));
    return d;
}
__device__ __forceinline__ float2 unpack2(unsigned long long v) {
    float2 r;
    asm("mov.b64 {%0, %1}, %2;" : "=f"(r.x), "=f"(r.y) : "l"(v));
    return r;
}
__device__ __forceinline__ unsigned long long mul2(unsigned long long a,
                                                   unsigned long long b) {
    unsigned long long d;
    asm("mul.rn.f32x2 %0, %1, %2;" : "=l"(d) : "l"(a), "l"(b));
    return d;
}
// pack fp16x2: low half = x (first elem in memory), high = y
__device__ __forceinline__ uint32_t pack_f16x2(float x, float y) {
    uint32_t r;
    asm("cvt.rn.f16x2.f32 %0, %1, %2;" : "=r"(r) : "f"(y), "f"(x));
    return r;
}
__device__ __forceinline__ uint32_t smem_u32(const void* p) {
    uint32_t a;
    asm("{ .reg .u64 t; cvta.to.shared.u64 t, %1; cvt.u32.u64 %0, t; }" : "=r"(a) : "l"(p));
    return a;
}
__device__ __forceinline__ void cp16(uint32_t dst, const void* src) {
    asm volatile("cp.async.cg.shared.global [%0], [%1], 16;" :: "r"(dst), "l"(src));
}
#define CP_COMMIT() asm volatile("cp.async.commit_group;" ::: "memory")
#define CP_WAIT0()  asm volatile("cp.async.wait_group 0;" ::: "memory")
#define CP_WAIT1()  asm volatile("cp.async.wait_group 1;" ::: "memory")
#define SWZ(o) ((o) ^ (((o) >> 3) & 0x70))

__device__ __forceinline__ void ldsm4(uint32_t& r0, uint32_t& r1, uint32_t& r2,
                                      uint32_t& r3, uint32_t addr) {
    asm volatile("ldmatrix.sync.aligned.m8n8.x4.shared.b16 {%0,%1,%2,%3}, [%4];"
        : "=r"(r0), "=r"(r1), "=r"(r2), "=r"(r3) : "r"(addr));
}
__device__ __forceinline__ void mma16816(float* d, const uint32_t* a,
                                         uint32_t b0, uint32_t b1) {
    asm volatile(
        "mma.sync.aligned.m16n8k16.row.col.f32.f16.f16.f32 "
        "{%0,%1,%2,%3}, {%4,%5,%6,%7}, {%8,%9}, {%0,%1,%2,%3};"
        : "+f"(d[0]), "+f"(d[1]), "+f"(d[2]), "+f"(d[3])
        : "r"(a[0]), "r"(a[1]), "r"(a[2]), "r"(a[3]), "r"(b0), "r"(b1));
}

// =============================================================================
// prep A: validity flags f[m] = (sum_c x[m,c] > 0)
// =============================================================================
__global__ void __launch_bounds__(256) prep_flags(const float* __restrict__ x) {
    const int w = threadIdx.x >> 5, l = threadIdx.x & 31;
    const int r = blockIdx.x * 16 + w * 2 + (l >> 4);
    const float4 v = ((const float4*)(x + (size_t)r * NC))[l & 15];
    float s = v.x + v.y + v.z + v.w;
    #pragma unroll
    for (int o = 1; o < 16; o <<= 1) s += __shfl_xor_sync(0xffffffffu, s, o);
    if ((l & 15) == 0) g_flag[r] = (s > 0.0f) ? 1.0f : 0.0f;
}

// =============================================================================
// prep B: pack W into m16n8k16 B-fragment order, fp16 hi/lo split.
//   B[kc][n] = W[k_kp][c][n],  kc = c*16 + k_kp  (k_kp==15 -> 0 pad)
//   g_bfrag[(kstep*8+ntile)*32+lane] = { bh(k0,k0+1), bh(k0+8,k0+9),
//                                        bl(k0,k0+1), bl(k0+8,k0+9) }
// =============================================================================
__device__ __forceinline__ float wval(const float* W, int kc, int n) {
    const int k_kp = kc & 15, c = kc >> 4;
    return (k_kp < NK) ? W[((size_t)k_kp * NC + c) * ND + n] : 0.0f;
}
__global__ void __launch_bounds__(256) prep_w(const float* __restrict__ W) {
    const int g     = blockIdx.x * 256 + threadIdx.x;   // 64*8*32 = 16384
    const int lane  = g & 31;
    const int ntile = (g >> 5) & 7;
    const int kstep = g >> 8;                           // 0..63
    const int n  = ntile * 8 + (lane >> 2);
    const int kc = kstep * 16 + 2 * (lane & 3);
    float v[4] = { wval(W, kc,     n), wval(W, kc + 1, n),
                   wval(W, kc + 8, n), wval(W, kc + 9, n) };
    float h[4], l[4];
    #pragma unroll
    for (int i = 0; i < 4; i++) {
        h[i] = __half2float(__float2half_rn(v[i]));
        l[i] = v[i] - h[i];
    }
    g_bfrag[g] = make_uint4(pack_f16x2(h[0], h[1]), pack_f16x2(h[2], h[3]),
                            pack_f16x2(l[0], l[1]), pack_f16x2(l[2], l[3]));
}

// =============================================================================
// Stage 1 (R5 shape exactly; fp16 single-plane epilogue).
// One warp per query; 8 queries / 256-thread block.
// Phase A: lane = neighbor h -> w[h][k] in smem.
// Phase B: lane = channels (lane, lane+32): two independent LDG.32 per h
// (keeps MLP=2), 16 f32x2 k-pair accumulators, unroll 8.
// =============================================================================
__global__ void __launch_bounds__(256) kpconv_stage1(
    const float* __restrict__ q_pts, const float* __restrict__ s_pts,
    const int*   __restrict__ nbi,   const float* __restrict__ x,
    const float* __restrict__ kp)
{
    __shared__ __align__(16) float ws[8][NH][16];   // 16 KB
    __shared__ int idxs[8][NH];
    const int warp = threadIdx.x >> 5;
    const int lane = threadIdx.x & 31;
    const int n    = blockIdx.x * 8 + warp;

    // ---- phase A: lane = neighbor h ----
    const int idx = __ldg(&nbi[n * NH + lane]);
    const float qx = q_pts[n*3+0], qy = q_pts[n*3+1], qz = q_pts[n*3+2];
    const float dx = __ldg(&s_pts[idx*3+0]) - qx;
    const float dy = __ldg(&s_pts[idx*3+1]) - qy;
    const float dz = __ldg(&s_pts[idx*3+2]) - qz;
    const float vf = __ldg(&g_flag[idx]);
    #pragma unroll
    for (int k = 0; k < NK; k++) {
        const float ex = dx - kp[k*3+0];
        const float ey = dy - kp[k*3+1];
        const float ez = dz - kp[k*3+2];
        const float d2 = ex*ex + ey*ey + ez*ez;
        const float r  = __frsqrt_rn(fmaxf(d2, 1e-24f));
        ws[warp][lane][k] = fmaxf(1.0f - (d2 * r) * (1.0f / 1.2f), 0.0f);
    }
    ws[warp][lane][15] = 0.0f;
    idxs[warp][lane] = idx;
    const int cnt = __popc(__ballot_sync(0xffffffffu, vf > 0.0f));
    __syncwarp();

    // ---- phase B: lane = channel (c=lane and c=lane+32) ----
    unsigned long long a0[8], a1[8];
    #pragma unroll
    for (int j = 0; j < 8; j++) { a0[j] = 0ull; a1[j] = 0ull; }

    #pragma unroll 8
    for (int h = 0; h < NH; h++) {
        const int ih = idxs[warp][h];
        const float* xr = x + (size_t)ih * NC;
        const unsigned long long xx0 = splat2(__ldg(&xr[lane]));
        const unsigned long long xx1 = splat2(__ldg(&xr[lane + 32]));
        const ulonglong2* wp = (const ulonglong2*)&ws[warp][h][0];
        #pragma unroll
        for (int j = 0; j < 4; j++) {
            const ulonglong2 w2 = wp[j];
            a0[2*j+0] = ffma2(w2.x, xx0, a0[2*j+0]);
            a0[2*j+1] = ffma2(w2.y, xx0, a0[2*j+1]);
            a1[2*j+0] = ffma2(w2.x, xx1, a1[2*j+0]);
            a1[2*j+1] = ffma2(w2.y, xx1, a1[2*j+1]);
        }
    }

    const float inv = 1.0f / (float)(cnt > 0 ? cnt : 1);
    const unsigned long long inv2 = splat2(inv);

    // ---- epilogue: single fp16 plane, 2x STG.128 per channel ----
    #pragma unroll
    for (int half = 0; half < 2; half++) {
        const int c = lane + half * 32;
        const unsigned long long* acc = half ? a1 : a0;
        uint32_t p[8];
        #pragma unroll
        for (int j = 0; j < 8; j++) {
            const float2 s = unpack2(mul2(acc[j], inv2));
            p[j] = pack_f16x2(s.x, s.y);
        }
        uint4* pa = (uint4*)(g_a + (size_t)n * KC2 + c * 16);
        pa[0] = make_uint4(p[0], p[1], p[2], p[3]);
        pa[1] = make_uint4(p[4], p[5], p[6], p[7]);
    }
}

// =============================================================================
// Stage 2 (v3): fp16 2-product (A*Bh + A*Bl). BM=128, single A plane.
// Smem per buffer: A 16K | Bfrag 16K = 32K; x2 = 64 KB -> 3 blocks/SM.
// Warp w owns m-tile rows [w*16, w*16+16), all 8 n-tiles; 16 MMAs/warp/ks.
// =============================================================================
#define S2_THREADS 256
#define BUFB 32768
#define OFF_BF  16384
#define SM_TOT  (2 * BUFB)

__device__ __forceinline__ void s2_issue(uint32_t sb, int buf, int chunk, int tid,
                                         const char* Apl) {
    const uint32_t base = sb + buf * BUFB;
    #pragma unroll
    for (int i = 0; i < 4; i++) {                 // A: 128 rows x 128B
        const int ch  = i * S2_THREADS + tid;     // 0..1023
        const int rr  = ch >> 3;
        const int c16 = (ch & 7) * 16;
        const uint32_t d = SWZ((uint32_t)(rr * 128 + c16));
        cp16(base + d, Apl + (size_t)rr * 2048 + chunk * 128 + c16);
    }
    #pragma unroll
    for (int i = 0; i < 4; i++) {                 // B frags: 16 KB linear
        const int ch = i * S2_THREADS + tid;      // 0..1023
        cp16(base + OFF_BF + ch * 16, (const char*)g_bfrag + ((size_t)chunk * 1024 + ch) * 16);
    }
}

__global__ void __launch_bounds__(S2_THREADS) kpconv_stage2(float* __restrict__ out) {
    extern __shared__ __align__(1024) char smem[];
    const uint32_t sb = smem_u32(smem);
    const int tid  = threadIdx.x;
    const int wid  = tid >> 5;
    const int lane = tid & 31;
    const int n0   = blockIdx.x * 128;
    const int m0   = wid * 16;

    const char* Apl = (const char*)(g_a + (size_t)n0 * KC2);

    float d[8][4];
    #pragma unroll
    for (int t = 0; t < 8; t++)
        #pragma unroll
        for (int j = 0; j < 4; j++) d[t][j] = 0.0f;

    const uint32_t arow  = (uint32_t)(m0 + (lane & 15));
    const uint32_t ahalf = (uint32_t)((lane >> 4) * 16);   // bytes

    s2_issue(sb, 0, 0, tid, Apl);
    CP_COMMIT();

    for (int ch = 0; ch < 16; ch++) {
        if (ch + 1 < 16) {
            s2_issue(sb, (ch + 1) & 1, ch + 1, tid, Apl);
            CP_COMMIT();
            CP_WAIT1();
        } else {
            CP_WAIT0();
        }
        __syncthreads();

        const uint32_t base = sb + (ch & 1) * BUFB;
        #pragma unroll
        for (int ks = 0; ks < 4; ks++) {
            const uint32_t aoff = SWZ(arow * 128 + (uint32_t)(ks * 32) + ahalf);
            uint32_t a[4];
            ldsm4(a[0], a[1], a[2], a[3], base + aoff);
            const uint32_t bbase = base + OFF_BF + (uint32_t)(ks * 8 * 32 + lane) * 16;
            #pragma unroll
            for (int nt = 0; nt < 8; nt++) {
                uint4 bf;
                asm volatile("ld.shared.v4.b32 {%0,%1,%2,%3}, [%4];"
                    : "=r"(bf.x), "=r"(bf.y), "=r"(bf.z), "=r"(bf.w)
                    : "r"(bbase + (uint32_t)(nt * 32 * 16)));
                mma16816(d[nt], a, bf.x, bf.y);   // A * Bhi
                mma16816(d[nt], a, bf.z, bf.w);   // A * Blo
            }
        }
        __syncthreads();
    }

    const int r0 = n0 + m0 + (lane >> 2);
    const int r1 = r0 + 8;
    const int c0 = (lane & 3) * 2;
    #pragma unroll
    for (int nt = 0; nt < 8; nt++) {
        const int c = nt * 8 + c0;
        if (r0 < NQ) *(float2*)(out + (size_t)r0 * ND + c) = make_float2(d[nt][0], d[nt][1]);
        if (r1 < NQ) *(float2*)(out + (size_t)r1 * ND + c) = make_float2(d[nt][2], d[nt][3]);
    }
}

// =============================================================================
extern "C" void kernel_launch(void* const* d_in, const int* in_sizes, int n_in,
                              void* d_out, int out_size) {
    const float* q_pts = (const float*)d_in[0];
    const float* s_pts = (const float*)d_in[1];
    const int*   nbi   = (const int*)  d_in[2];
    const float* x     = (const float*)d_in[3];
    const float* kp    = (const float*)d_in[4];
    const float* W     = (const float*)d_in[5];
    float* out = (float*)d_out;

    cudaFuncSetAttribute(kpconv_stage2, cudaFuncAttributeMaxDynamicSharedMemorySize, SM_TOT);

    prep_flags<<<NMS / 16, 256>>>(x);
    prep_w<<<64, 256>>>(W);
    kpconv_stage1<<<NQ / 8, 256>>>(q_pts, s_pts, nbi, x, kp);
    kpconv_stage2<<<KPAD / 128, S2_THREADS, SM_TOT>>>(out);
}

// round 11
// speedup vs baseline: 2.1730x; 1.5289x over previous
#include <cuda_runtime.h>
#include <cuda_fp16.h>
#include <cstdint>

// ---------------- problem constants ----------------
#define NQ   50000
#define NMS  50000
#define NH   32
#define NK   15
#define NC   64
#define ND   64
#define KPAD 50048          // NQ padded to multiple of 128
#define KC2  1024           // 64 channels * 16 (k padded 15->16)

// scratch: SINGLE fp16 plane of weighted[n][c*16+k] (normalization folded in)
__device__ __half g_a[(size_t)KPAD * KC2];           // ~102 MB
__device__ uint2  g_bfrag[64 * 8 * 32];              // B fp16 fragments, 128 KB
__device__ float  g_flag[NMS];                       // rowsum>0 flags

// ---------------- helpers ----------------
__device__ __forceinline__ unsigned long long ffma2(unsigned long long a,
                                                    unsigned long long b,
                                                    unsigned long long c) {
    unsigned long long d;
    asm("fma.rn.f32x2 %0, %1, %2, %3;" : "=l"(d) : "l"(a), "l"(b), "l"(c));
    return d;
}
__device__ __forceinline__ unsigned long long splat2(float v) {
    unsigned long long d;
    asm("mov.b64 %0, {%1, %1};" : "=l"(d) : "f"(v));
    return d;
}
__device__ __forceinline__ float2 unpack2(unsigned long long v) {
    float2 r;
    asm("mov.b64 {%0, %1}, %2;" : "=f"(r.x), "=f"(r.y) : "l"(v));
    return r;
}
__device__ __forceinline__ unsigned long long mul2(unsigned long long a,
                                                   unsigned long long b) {
    unsigned long long d;
    asm("mul.rn.f32x2 %0, %1, %2;" : "=l"(d) : "l"(a), "l"(b));
    return d;
}
// pack fp16x2: low half = x (first elem in memory), high = y
__device__ __forceinline__ uint32_t pack_f16x2(float x, float y) {
    uint32_t r;
    asm("cvt.rn.f16x2.f32 %0, %1, %2;" : "=r"(r) : "f"(y), "f"(x));
    return r;
}
__device__ __forceinline__ uint32_t smem_u32(const void* p) {
    uint32_t a;
    asm("{ .reg .u64 t; cvta.to.shared.u64 t, %1; cvt.u32.u64 %0, t; }" : "=r"(a) : "l"(p));
    return a;
}
__device__ __forceinline__ void cp16(uint32_t dst, const void* src) {
    asm volatile("cp.async.cg.shared.global [%0], [%1], 16;" :: "r"(dst), "l"(src));
}
#define CP_COMMIT() asm volatile("cp.async.commit_group;" ::: "memory")
#define CP_WAIT0()  asm volatile("cp.async.wait_group 0;" ::: "memory")
#define CP_WAIT1()  asm volatile("cp.async.wait_group 1;" ::: "memory")
#define SWZ(o) ((o) ^ (((o) >> 3) & 0x70))

__device__ __forceinline__ void ldsm4(uint32_t& r0, uint32_t& r1, uint32_t& r2,
                                      uint32_t& r3, uint32_t addr) {
    asm volatile("ldmatrix.sync.aligned.m8n8.x4.shared.b16 {%0,%1,%2,%3}, [%4];"
        : "=r"(r0), "=r"(r1), "=r"(r2), "=r"(r3) : "r"(addr));
}
__device__ __forceinline__ void mma16816(float* d, const uint32_t* a,
                                         uint32_t b0, uint32_t b1) {
    asm volatile(
        "mma.sync.aligned.m16n8k16.row.col.f32.f16.f16.f32 "
        "{%0,%1,%2,%3}, {%4,%5,%6,%7}, {%8,%9}, {%0,%1,%2,%3};"
        : "+f"(d[0]), "+f"(d[1]), "+f"(d[2]), "+f"(d[3])
        : "r"(a[0]), "r"(a[1]), "r"(a[2]), "r"(a[3]), "r"(b0), "r"(b1));
}

// =============================================================================
// prep A: validity flags f[m] = (sum_c x[m,c] > 0)
// =============================================================================
__global__ void __launch_bounds__(256) prep_flags(const float* __restrict__ x) {
    const int w = threadIdx.x >> 5, l = threadIdx.x & 31;
    const int r = blockIdx.x * 16 + w * 2 + (l >> 4);
    const float4 v = ((const float4*)(x + (size_t)r * NC))[l & 15];
    float s = v.x + v.y + v.z + v.w;
    #pragma unroll
    for (int o = 1; o < 16; o <<= 1) s += __shfl_xor_sync(0xffffffffu, s, o);
    if ((l & 15) == 0) g_flag[r] = (s > 0.0f) ? 1.0f : 0.0f;
}

// =============================================================================
// prep B: pack W into m16n8k16 B-fragment order (single fp16 plane).
//   B[kc][n] = W[k_kp][c][n],  kc = c*16 + k_kp  (k_kp==15 -> 0 pad)
//   g_bfrag[(kstep*8+ntile)*32+lane] = { b(k0,k0+1), b(k0+8,k0+9) }
// =============================================================================
__device__ __forceinline__ float wval(const float* W, int kc, int n) {
    const int k_kp = kc & 15, c = kc >> 4;
    return (k_kp < NK) ? W[((size_t)k_kp * NC + c) * ND + n] : 0.0f;
}
__global__ void __launch_bounds__(256) prep_w(const float* __restrict__ W) {
    const int g     = blockIdx.x * 256 + threadIdx.x;   // 64*8*32 = 16384
    const int lane  = g & 31;
    const int ntile = (g >> 5) & 7;
    const int kstep = g >> 8;                           // 0..63
    const int n  = ntile * 8 + (lane >> 2);
    const int kc = kstep * 16 + 2 * (lane & 3);
    g_bfrag[g] = make_uint2(
        pack_f16x2(wval(W, kc,     n), wval(W, kc + 1, n)),
        pack_f16x2(wval(W, kc + 8, n), wval(W, kc + 9, n)));
}

// =============================================================================
// Stage 1 (R5 shape + dead-neighbor compaction).
// One warp per query; 8 queries / 256-thread block.
// Phase A: lane = neighbor h; computes w[h][k]; neighbors with ALL w==0 are
//          dropped via warp ballot + compaction (warp-uniform, no divergence).
// Phase B: lane = channels (lane, lane+32); loops only over nact active
//          neighbors; 16 f32x2 k-pair accumulators.
// =============================================================================
__global__ void __launch_bounds__(256) kpconv_stage1(
    const float* __restrict__ q_pts, const float* __restrict__ s_pts,
    const int*   __restrict__ nbi,   const float* __restrict__ x,
    const float* __restrict__ kp)
{
    __shared__ __align__(16) float ws[8][NH][16];   // 16 KB
    __shared__ int idxs[8][NH];
    const int warp = threadIdx.x >> 5;
    const int lane = threadIdx.x & 31;
    const int n    = blockIdx.x * 8 + warp;

    // ---- phase A: lane = neighbor h ----
    const int idx = __ldg(&nbi[n * NH + lane]);
    const float qx = q_pts[n*3+0], qy = q_pts[n*3+1], qz = q_pts[n*3+2];
    const float dx = __ldg(&s_pts[idx*3+0]) - qx;
    const float dy = __ldg(&s_pts[idx*3+1]) - qy;
    const float dz = __ldg(&s_pts[idx*3+2]) - qz;
    const float vf = __ldg(&g_flag[idx]);

    float wk[16];
    bool anyw = false;
    #pragma unroll
    for (int k = 0; k < NK; k++) {
        const float ex = dx - kp[k*3+0];
        const float ey = dy - kp[k*3+1];
        const float ez = dz - kp[k*3+2];
        const float d2 = ex*ex + ey*ey + ez*ez;
        const float r  = __frsqrt_rn(fmaxf(d2, 1e-24f));
        const float w  = fmaxf(1.0f - (d2 * r) * (1.0f / 1.2f), 0.0f);
        wk[k] = w;
        anyw = anyw || (w > 0.0f);
    }
    wk[15] = 0.0f;

    const uint32_t amask = __ballot_sync(0xffffffffu, anyw);
    const int nact = __popc(amask);
    const int cnt  = __popc(__ballot_sync(0xffffffffu, vf > 0.0f));
    if (anyw) {
        const int pos = __popc(amask & ((1u << lane) - 1u));
        #pragma unroll
        for (int k = 0; k < 16; k++) ws[warp][pos][k] = wk[k];
        idxs[warp][pos] = idx;
    }
    __syncwarp();

    // ---- phase B: lane = channel (c=lane and c=lane+32), active h only ----
    unsigned long long a0[8], a1[8];
    #pragma unroll
    for (int j = 0; j < 8; j++) { a0[j] = 0ull; a1[j] = 0ull; }

    #pragma unroll 4
    for (int h = 0; h < nact; h++) {
        const int ih = idxs[warp][h];
        const float* xr = x + (size_t)ih * NC;
        const unsigned long long xx0 = splat2(__ldg(&xr[lane]));
        const unsigned long long xx1 = splat2(__ldg(&xr[lane + 32]));
        const ulonglong2* wp = (const ulonglong2*)&ws[warp][h][0];
        #pragma unroll
        for (int j = 0; j < 4; j++) {
            const ulonglong2 w2 = wp[j];
            a0[2*j+0] = ffma2(w2.x, xx0, a0[2*j+0]);
            a0[2*j+1] = ffma2(w2.y, xx0, a0[2*j+1]);
            a1[2*j+0] = ffma2(w2.x, xx1, a1[2*j+0]);
            a1[2*j+1] = ffma2(w2.y, xx1, a1[2*j+1]);
        }
    }

    const float inv = 1.0f / (float)(cnt > 0 ? cnt : 1);
    const unsigned long long inv2 = splat2(inv);

    // ---- epilogue: single fp16 plane, 2x STG.128 per channel ----
    #pragma unroll
    for (int half = 0; half < 2; half++) {
        const int c = lane + half * 32;
        const unsigned long long* acc = half ? a1 : a0;
        uint32_t p[8];
        #pragma unroll
        for (int j = 0; j < 8; j++) {
            const float2 s = unpack2(mul2(acc[j], inv2));
            p[j] = pack_f16x2(s.x, s.y);
        }
        uint4* pa = (uint4*)(g_a + (size_t)n * KC2 + c * 16);
        pa[0] = make_uint4(p[0], p[1], p[2], p[3]);
        pa[1] = make_uint4(p[4], p[5], p[6], p[7]);
    }
}

// =============================================================================
// Stage 2 (v4): single fp16 product out = A x B. BM=128.
// Smem per buffer: A 16K | Bfrag 8K = 24K; x2 = 48 KB.
// Warp w owns m-tile rows [w*16, w*16+16), all 8 n-tiles; 8 MMAs/warp/ks.
// =============================================================================
#define S2_THREADS 256
#define BUFB 24576
#define OFF_BF  16384
#define SM_TOT  (2 * BUFB)

__device__ __forceinline__ void s2_issue(uint32_t sb, int buf, int chunk, int tid,
                                         const char* Apl) {
    const uint32_t base = sb + buf * BUFB;
    #pragma unroll
    for (int i = 0; i < 4; i++) {                 // A: 128 rows x 128B
        const int ch  = i * S2_THREADS + tid;     // 0..1023
        const int rr  = ch >> 3;
        const int c16 = (ch & 7) * 16;
        const uint32_t d = SWZ((uint32_t)(rr * 128 + c16));
        cp16(base + d, Apl + (size_t)rr * 2048 + chunk * 128 + c16);
    }
    #pragma unroll
    for (int i = 0; i < 2; i++) {                 // B frags: 8 KB linear
        const int ch = i * S2_THREADS + tid;      // 0..511
        cp16(base + OFF_BF + ch * 16, (const char*)g_bfrag + ((size_t)chunk * 512 + ch) * 16);
    }
}

__global__ void __launch_bounds__(S2_THREADS) kpconv_stage2(float* __restrict__ out) {
    extern __shared__ __align__(1024) char smem[];
    const uint32_t sb = smem_u32(smem);
    const int tid  = threadIdx.x;
    const int wid  = tid >> 5;
    const int lane = tid & 31;
    const int n0   = blockIdx.x * 128;
    const int m0   = wid * 16;

    const char* Apl = (const char*)(g_a + (size_t)n0 * KC2);

    float d[8][4];
    #pragma unroll
    for (int t = 0; t < 8; t++)
        #pragma unroll
        for (int j = 0; j < 4; j++) d[t][j] = 0.0f;

    const uint32_t arow  = (uint32_t)(m0 + (lane & 15));
    const uint32_t ahalf = (uint32_t)((lane >> 4) * 16);   // bytes

    s2_issue(sb, 0, 0, tid, Apl);
    CP_COMMIT();

    for (int ch = 0; ch < 16; ch++) {
        if (ch + 1 < 16) {
            s2_issue(sb, (ch + 1) & 1, ch + 1, tid, Apl);
            CP_COMMIT();
            CP_WAIT1();
        } else {
            CP_WAIT0();
        }
        __syncthreads();

        const uint32_t base = sb + (ch & 1) * BUFB;
        #pragma unroll
        for (int ks = 0; ks < 4; ks++) {
            const uint32_t aoff = SWZ(arow * 128 + (uint32_t)(ks * 32) + ahalf);
            uint32_t a[4];
            ldsm4(a[0], a[1], a[2], a[3], base + aoff);
            const uint32_t bbase = base + OFF_BF + (uint32_t)(ks * 8 * 32 + lane) * 8;
            #pragma unroll
            for (int nt = 0; nt < 8; nt++) {
                uint2 bf;
                asm volatile("ld.shared.v2.b32 {%0,%1}, [%2];"
                    : "=r"(bf.x), "=r"(bf.y)
                    : "r"(bbase + (uint32_t)(nt * 32 * 8)));
                mma16816(d[nt], a, bf.x, bf.y);
            }
        }
        __syncthreads();
    }

    const int r0 = n0 + m0 + (lane >> 2);
    const int r1 = r0 + 8;
    const int c0 = (lane & 3) * 2;
    #pragma unroll
    for (int nt = 0; nt < 8; nt++) {
        const int c = nt * 8 + c0;
        if (r0 < NQ) *(float2*)(out + (size_t)r0 * ND + c) = make_float2(d[nt][0], d[nt][1]);
        if (r1 < NQ) *(float2*)(out + (size_t)r1 * ND + c) = make_float2(d[nt][2], d[nt][3]);
    }
}

// =============================================================================
extern "C" void kernel_launch(void* const* d_in, const int* in_sizes, int n_in,
                              void* d_out, int out_size) {
    const float* q_pts = (const float*)d_in[0];
    const float* s_pts = (const float*)d_in[1];
    const int*   nbi   = (const int*)  d_in[2];
    const float* x     = (const float*)d_in[3];
    const float* kp    = (const float*)d_in[4];
    const float* W     = (const float*)d_in[5];
    float* out = (float*)d_out;

    cudaFuncSetAttribute(kpconv_stage2, cudaFuncAttributeMaxDynamicSharedMemorySize, SM_TOT);

    prep_flags<<<NMS / 16, 256>>>(x);
    prep_w<<<64, 256>>>(W);
    kpconv_stage1<<<NQ / 8, 256>>>(q_pts, s_pts, nbi, x, kp);
    kpconv_stage2<<<KPAD / 128, S2_THREADS, SM_TOT>>>(out);
}